// round 9
// baseline (speedup 1.0000x reference)
#include <cuda_runtime.h>
#include <cuda_bf16.h>
#include <cstdint>

#define N_NODES 8192
#define D 128
#define KNBR 8
#define LN_EPS 1e-5f

#define M_PLAIN 0
#define M_RELU  1
#define M_LN    2

#define MTILE 32
// SMEM: Ah[32x128 bf16]=8K @0, Al=8K @8192; LN sC overlays (32*132*4=16896)
#define OFF_AL 8192
#define SMEM_TOTAL 17152
#define WTILE_BYTES 32768   // one frag-packed W chunk [128n x 128k] bf16

// ---------------- scratch (device globals: no allocation allowed) ----------
__device__ float g_buf0[N_NODES * D];
__device__ float g_buf1[N_NODES * D];
__device__ float g_buf2[N_NODES * D];
__device__ float g_buf3[N_NODES * D];
__device__ float g_dinv[N_NODES];
__device__ int   g_kcnt[N_NODES];
__device__ __align__(16) int g_gn[N_NODES * KNBR];      // gcn kept list, pad=i
__device__ __align__(16) int g_pooln[N_NODES * KNBR];   // pool list, pad=first
__device__ float g_pmul[N_NODES];                       // 0 if leaf else 1
// W pre-split hi/lo, packed in mma B-fragment order:
// idx = ((ks*4 + wn)*32 + lane)*8 + (ntile*2 + reg)
__device__ __align__(16) unsigned char g_wh[10 * WTILE_BYTES];
__device__ __align__(16) unsigned char g_wl[10 * WTILE_BYTES];

// ---------------- job descriptors -------------------------------------------
struct GJob {
    const float* A1; const float* psrc;
    const float* bias; const float* res; const float* lng; const float* lnb;
    float* out;
    int wchunk, nchunks, mode, ostride, ooff;
};
struct PJob {
    const float* nxt; const float* res; const float* lng; const float* lnb;
    float* out;
    int ostride, ooff;
};

// ---------------- helpers ---------------------------------------------------
__device__ __forceinline__ uint32_t smem_u32(const void* p) {
    uint32_t a;
    asm("{ .reg .u64 t; cvta.to.shared.u64 t, %1; cvt.u32.u64 %0, t; }"
        : "=r"(a) : "l"(p));
    return a;
}
__device__ __forceinline__ void ldsm4(uint32_t addr, uint32_t* r) {
    asm volatile("ldmatrix.sync.aligned.m8n8.x4.shared.b16 {%0,%1,%2,%3}, [%4];"
                 : "=r"(r[0]), "=r"(r[1]), "=r"(r[2]), "=r"(r[3]) : "r"(addr));
}
__device__ __forceinline__ void mma_bf16(float* d, const uint32_t* a,
                                         uint32_t b0, uint32_t b1) {
    asm volatile(
        "mma.sync.aligned.m16n8k16.row.col.f32.bf16.bf16.f32 "
        "{%0,%1,%2,%3}, {%4,%5,%6,%7}, {%8,%9}, {%0,%1,%2,%3};"
        : "+f"(d[0]), "+f"(d[1]), "+f"(d[2]), "+f"(d[3])
        : "r"(a[0]), "r"(a[1]), "r"(a[2]), "r"(a[3]), "r"(b0), "r"(b1));
}
static __device__ __forceinline__ uint32_t bf2u(__nv_bfloat162 v) {
    return *reinterpret_cast<uint32_t*>(&v);
}
// pack 8 consecutive floats -> hi uint4 / lo uint4 (bf16 pairs)
__device__ __forceinline__ void split8(const float* f, uint4& hi, uint4& lo) {
    __nv_bfloat16 h[8];
    float l[8];
#pragma unroll
    for (int e = 0; e < 8; ++e) {
        h[e] = __float2bfloat16(f[e]);
        l[e] = f[e] - __bfloat162float(h[e]);
    }
    hi.x = bf2u(__halves2bfloat162(h[0], h[1]));
    hi.y = bf2u(__halves2bfloat162(h[2], h[3]));
    hi.z = bf2u(__halves2bfloat162(h[4], h[5]));
    hi.w = bf2u(__halves2bfloat162(h[6], h[7]));
    lo.x = bf2u(__floats2bfloat162_rn(l[0], l[1]));
    lo.y = bf2u(__floats2bfloat162_rn(l[2], l[3]));
    lo.z = bf2u(__floats2bfloat162_rn(l[4], l[5]));
    lo.w = bf2u(__floats2bfloat162_rn(l[6], l[7]));
}

// ---------------- prep: blocks 0-9 pack W frags, blocks 10-41 graph --------
__global__ void prep_all_kernel(const int* __restrict__ neigh,
                                const int* __restrict__ nbrc,
                                const float* __restrict__ gW,
                                const float* __restrict__ pW,
                                const float* __restrict__ mW) {
    int c = blockIdx.x, tid = threadIdx.x;
    if (c >= 10) {
        int i = (c - 10) * 256 + tid;
        int cnt = nbrc[i];
        cnt = cnt > KNBR ? KNBR : (cnt < 0 ? 0 : cnt);
        int first = cnt > 0 ? neigh[i * KNBR] : 0;
#pragma unroll
        for (int k = 0; k < KNBR; ++k)
            g_pooln[i * KNBR + k] = k < cnt ? neigh[i * KNBR + k] : first;
        g_pmul[i] = cnt > 0 ? 1.f : 0.f;
        int kept[KNBR];
        int kc = 0;
        for (int k = 0; k < cnt; ++k) {
            int nb = neigh[i * KNBR + k];
            if (nb == i) continue;
            bool dup = false;
            for (int t = 0; t < kc; ++t) if (kept[t] == nb) dup = true;
            if (!dup) kept[kc++] = nb;
        }
#pragma unroll
        for (int k = 0; k < KNBR; ++k)
            g_gn[i * KNBR + k] = k < kc ? kept[k] : i;
        g_kcnt[i] = kc;
        g_dinv[i] = rsqrtf((float)(kc + 1));
        return;
    }
    const float* src;
    int stride, coloff;
    if (c < 3)       { src = gW + c * 16384; stride = 128; coloff = 0; }
    else if (c == 3) { src = pW;             stride = 128; coloff = 0; }
    else { int l = (c - 4) >> 1, h = (c - 4) & 1;
           src = mW + l * 32768; stride = 256; coloff = h * 128; }
    uint32_t* wh = (uint32_t*)(g_wh + c * WTILE_BYTES);
    uint32_t* wl = (uint32_t*)(g_wl + c * WTILE_BYTES);
    // B-frag order: idx = ((ks*4+wn)*32+lane)*8 + (j*2+w)
    // n = wn*32 + j*8 + lane/4 ; k = ks*16 + w*8 + (lane%4)*2
    for (int idx = tid; idx < 8192; idx += 256) {
        int r    = idx & 7;
        int lane = (idx >> 3) & 31;
        int wn   = (idx >> 8) & 3;
        int ks   = idx >> 10;
        int n = wn * 32 + (r >> 1) * 8 + (lane >> 2);
        int k = ks * 16 + (r & 1) * 8 + (lane & 3) * 2;
        float a = src[n * stride + coloff + k];
        float b = src[n * stride + coloff + k + 1];
        __nv_bfloat16 ha = __float2bfloat16(a), hb = __float2bfloat16(b);
        wh[idx] = bf2u(__halves2bfloat162(ha, hb));
        wl[idx] = bf2u(__floats2bfloat162_rn(a - __bfloat162float(ha),
                                             b - __bfloat162float(hb)));
    }
}

// ---------------- GEMM body: out = [A1 | pool(psrc)] @ W^T + b -------------
// hi/lo split: D = Ah@Wh + Ah@Wl + Al@Wh (fp32 accum in fragments)
__device__ void gemm_body(const GJob& J, int bid, char* smem_raw) {
    const uint32_t sbase = smem_u32(smem_raw);
    const int tid = threadIdx.x, wid = tid >> 5, lane = tid & 31;
    const int wm = wid & 1, wn = wid >> 1;   // warp = rows wm*16..+15, cols wn*32..+31
    const int m0 = bid * MTILE;

    float acc[4][4];
#pragma unroll
    for (int j = 0; j < 4; ++j)
#pragma unroll
        for (int r = 0; r < 4; ++r) acc[j][r] = 0.f;

    const int lrow = lane & 15, lhalf = lane >> 4;
    const int rowA = wm * 16 + lrow;
    const uint32_t aswb = rowA * 256;                       // row byte base
    const int wfrag_off = (wn * 32 + lane) * 32;            // per-thread W frag base

    for (int c = 0; c < J.nchunks; ++c) {
        if (c) __syncthreads();
        if (c == 0) {
            // stage A1 rows 32 x 16 chunks -> hi/lo, swizzled
            for (int i = tid; i < 512; i += 256) {
                int r = i >> 4, ch = i & 15;
                float f[8];
                float4 f0 = *(const float4*)&J.A1[(m0 + r) * D + ch * 8];
                float4 f1 = *(const float4*)&J.A1[(m0 + r) * D + ch * 8 + 4];
                f[0] = f0.x; f[1] = f0.y; f[2] = f0.z; f[3] = f0.w;
                f[4] = f1.x; f[5] = f1.y; f[6] = f1.z; f[7] = f1.w;
                uint4 hi, lo;
                split8(f, hi, lo);
                uint32_t off = (uint32_t)r * 256 + ((uint32_t)(ch ^ (r & 7)) << 4);
                *(uint4*)(smem_raw + off) = hi;
                *(uint4*)(smem_raw + OFF_AL + off) = lo;
            }
        } else {
            // fused max-pool gather: A2[r] = pmul * max over 8 padded nbrs
            for (int i = tid; i < 512; i += 256) {
                int r = i >> 4, ch = i & 15;
                int node = m0 + r;
                const int4* nl = (const int4*)(g_pooln + node * KNBR);
                int4 na = nl[0], nb = nl[1];
                float pm = g_pmul[node];
                const float* p = J.psrc + (size_t)ch * 8;
                float4 m0v = *(const float4*)&p[(size_t)na.x * D];
                float4 m1v = *(const float4*)&p[(size_t)na.x * D + 4];
                int idx[7] = { na.y, na.z, na.w, nb.x, nb.y, nb.z, nb.w };
#pragma unroll
                for (int t = 0; t < 7; ++t) {
                    float4 r0 = *(const float4*)&p[(size_t)idx[t] * D];
                    float4 r1 = *(const float4*)&p[(size_t)idx[t] * D + 4];
                    m0v.x = fmaxf(m0v.x, r0.x); m0v.y = fmaxf(m0v.y, r0.y);
                    m0v.z = fmaxf(m0v.z, r0.z); m0v.w = fmaxf(m0v.w, r0.w);
                    m1v.x = fmaxf(m1v.x, r1.x); m1v.y = fmaxf(m1v.y, r1.y);
                    m1v.z = fmaxf(m1v.z, r1.z); m1v.w = fmaxf(m1v.w, r1.w);
                }
                float f[8];
                f[0] = pm * m0v.x; f[1] = pm * m0v.y;
                f[2] = pm * m0v.z; f[3] = pm * m0v.w;
                f[4] = pm * m1v.x; f[5] = pm * m1v.y;
                f[6] = pm * m1v.z; f[7] = pm * m1v.w;
                uint4 hi, lo;
                split8(f, hi, lo);
                uint32_t off = (uint32_t)r * 256 + ((uint32_t)(ch ^ (r & 7)) << 4);
                *(uint4*)(smem_raw + off) = hi;
                *(uint4*)(smem_raw + OFF_AL + off) = lo;
            }
        }
        __syncthreads();

        const unsigned char* whp = g_wh + (J.wchunk + c) * WTILE_BYTES + wfrag_off;
        const unsigned char* wlp = g_wl + (J.wchunk + c) * WTILE_BYTES + wfrag_off;
#pragma unroll
        for (int pass = 0; pass < 3; ++pass) {
            const uint32_t aB = sbase + (pass < 2 ? 0 : OFF_AL);
            const unsigned char* wp = (pass == 1) ? wlp : whp;
#pragma unroll
            for (int ks = 0; ks < 8; ++ks) {
                const int ch = ks * 2 + lhalf;
                uint32_t a[4];
                ldsm4(aB + aswb + ((uint32_t)(ch ^ (rowA & 7)) << 4), a);
                uint4 q0 = *(const uint4*)(wp + ks * 4096);
                uint4 q1 = *(const uint4*)(wp + ks * 4096 + 16);
                mma_bf16(acc[0], a, q0.x, q0.y);
                mma_bf16(acc[1], a, q0.z, q0.w);
                mma_bf16(acc[2], a, q1.x, q1.y);
                mma_bf16(acc[3], a, q1.z, q1.w);
            }
        }
    }

    const int frow = lane >> 2, fcol = 2 * (lane & 3);

    if (J.mode != M_LN) {
#pragma unroll
        for (int j = 0; j < 4; ++j) {
            int ncol = wn * 32 + j * 8 + fcol;
            float2 bj = *(const float2*)&J.bias[ncol];
            int m = m0 + wm * 16 + frow;
            float2 v0 = make_float2(acc[j][0] + bj.x, acc[j][1] + bj.y);
            float2 v1 = make_float2(acc[j][2] + bj.x, acc[j][3] + bj.y);
            if (J.mode == M_RELU) {
                v0.x = fmaxf(v0.x, 0.f); v0.y = fmaxf(v0.y, 0.f);
                v1.x = fmaxf(v1.x, 0.f); v1.y = fmaxf(v1.y, 0.f);
            }
            *(float2*)&J.out[m * J.ostride + J.ooff + ncol] = v0;
            *(float2*)&J.out[(m + 8) * J.ostride + J.ooff + ncol] = v1;
        }
        return;
    }

    // LN: relu(C+b) -> SMEM [32][132], then per-row LayerNorm with residual
    float* sC = (float*)smem_raw;
    __syncthreads();
#pragma unroll
    for (int j = 0; j < 4; ++j) {
        int ncol = wn * 32 + j * 8 + fcol;
        float2 bj = *(const float2*)&J.bias[ncol];
        int r = wm * 16 + frow;
        sC[r * 132 + ncol]           = fmaxf(acc[j][0] + bj.x, 0.f);
        sC[r * 132 + ncol + 1]       = fmaxf(acc[j][1] + bj.y, 0.f);
        sC[(r + 8) * 132 + ncol]     = fmaxf(acc[j][2] + bj.x, 0.f);
        sC[(r + 8) * 132 + ncol + 1] = fmaxf(acc[j][3] + bj.y, 0.f);
    }
    __syncthreads();

    {
        const int row = tid >> 3, q = tid & 7;     // 8 threads per row
        const int m = m0 + row;
        float v[16];
        float s = 0.f, ss = 0.f;
#pragma unroll
        for (int t = 0; t < 4; ++t) {
            int col = q * 16 + t * 4;
            float4 cv = *(float4*)&sC[row * 132 + col];
            float4 rv = *(const float4*)&J.res[m * D + col];
            v[4 * t + 0] = cv.x + rv.x; v[4 * t + 1] = cv.y + rv.y;
            v[4 * t + 2] = cv.z + rv.z; v[4 * t + 3] = cv.w + rv.w;
            s  += v[4 * t] + v[4 * t + 1] + v[4 * t + 2] + v[4 * t + 3];
            ss += v[4 * t] * v[4 * t] + v[4 * t + 1] * v[4 * t + 1] +
                  v[4 * t + 2] * v[4 * t + 2] + v[4 * t + 3] * v[4 * t + 3];
        }
#pragma unroll
        for (int off = 1; off < 8; off <<= 1) {
            s  += __shfl_xor_sync(0xffffffffu, s,  off);
            ss += __shfl_xor_sync(0xffffffffu, ss, off);
        }
        float mean = s * (1.0f / 128.0f);
        float rstd = rsqrtf(ss * (1.0f / 128.0f) - mean * mean + LN_EPS);
#pragma unroll
        for (int t = 0; t < 4; ++t) {
            int col = q * 16 + t * 4;
            float4 gj = *(const float4*)&J.lng[col];
            float4 oj = *(const float4*)&J.lnb[col];
            float4 o;
            o.x = (v[4 * t + 0] - mean) * rstd * gj.x + oj.x;
            o.y = (v[4 * t + 1] - mean) * rstd * gj.y + oj.y;
            o.z = (v[4 * t + 2] - mean) * rstd * gj.z + oj.z;
            o.w = (v[4 * t + 3] - mean) * rstd * gj.w + oj.w;
            *(float4*)&J.out[m * J.ostride + J.ooff + col] = o;
        }
    }
}

// ---------------- prop body: 64 nodes per block, warp per node -------------
__device__ void prop_body(const PJob& P, int blk) {
    const int lane = threadIdx.x & 31, wid = threadIdx.x >> 5;
    const int base = blk * 64 + wid * 8;
    for (int t = 0; t < 8; ++t) {
        const int i = base + t;
        const float di = g_dinv[i];
        float4 s4 = ((const float4*)(P.nxt + (size_t)i * D))[lane];
        float4 acc = make_float4(di * s4.x, di * s4.y, di * s4.z, di * s4.w);
        const int kc = g_kcnt[i];
        const int* kn = g_gn + i * KNBR;
        for (int k = 0; k < kc; ++k) {
            int j = kn[k];
            float dj = g_dinv[j];
            float4 r = ((const float4*)(P.nxt + (size_t)j * D))[lane];
            acc.x += dj * r.x; acc.y += dj * r.y;
            acc.z += dj * r.z; acc.w += dj * r.w;
        }
        float4 rr = ((const float4*)(P.res + (size_t)i * D))[lane];
        float4 v;
        v.x = fmaxf(di * acc.x, 0.f) + rr.x;
        v.y = fmaxf(di * acc.y, 0.f) + rr.y;
        v.z = fmaxf(di * acc.z, 0.f) + rr.z;
        v.w = fmaxf(di * acc.w, 0.f) + rr.w;
        float s  = v.x + v.y + v.z + v.w;
        float ss = v.x * v.x + v.y * v.y + v.z * v.z + v.w * v.w;
#pragma unroll
        for (int off = 16; off; off >>= 1) {
            s  += __shfl_xor_sync(0xffffffffu, s,  off);
            ss += __shfl_xor_sync(0xffffffffu, ss, off);
        }
        float mean = s * (1.0f / 128.0f);
        float rstd = rsqrtf(ss * (1.0f / 128.0f) - mean * mean + LN_EPS);
        float4 gj = ((const float4*)P.lng)[lane];
        float4 oj = ((const float4*)P.lnb)[lane];
        float4 o;
        o.x = (v.x - mean) * rstd * gj.x + oj.x;
        o.y = (v.y - mean) * rstd * gj.y + oj.y;
        o.z = (v.z - mean) * rstd * gj.z + oj.z;
        o.w = (v.w - mean) * rstd * gj.w + oj.w;
        *(float4*)&P.out[(size_t)i * P.ostride + P.ooff + 4 * lane] = o;
    }
}

#define GB (N_NODES / MTILE)    // 256 gemm tiles
#define PB (N_NODES / 64)       // 128 prop blocks

// ---------------- named step kernels (distinct for ncu attribution) --------
__global__ __launch_bounds__(256, 3) void k_g2(GJob g0, GJob g1) {
    extern __shared__ __align__(256) char smem_raw[];
    int b = blockIdx.x;
    if (b < GB) gemm_body(g0, b, smem_raw);
    else        gemm_body(g1, b - GB, smem_raw);
}
__global__ __launch_bounds__(256, 3) void k_gp(GJob g, PJob p) {
    extern __shared__ __align__(256) char smem_raw[];
    int b = blockIdx.x;
    if (b < GB) gemm_body(g, b, smem_raw);
    else        prop_body(p, b - GB);
}
__global__ __launch_bounds__(256, 3) void k_g1(GJob g) {
    extern __shared__ __align__(256) char smem_raw[];
    gemm_body(g, blockIdx.x, smem_raw);
}
__global__ __launch_bounds__(256) void k_p(PJob p) {
    prop_body(p, blockIdx.x);
}

// ---------------- driver ----------------------------------------------------
extern "C" void kernel_launch(void* const* d_in, const int* in_sizes, int n_in,
                              void* d_out, int out_size) {
    const float* x   = (const float*)d_in[0];
    const int*   nei = (const int*)  d_in[1];
    const int*   nbc = (const int*)  d_in[2];
    const float* gW  = (const float*)d_in[3];
    const float* gb  = (const float*)d_in[4];
    const float* glg = (const float*)d_in[5];
    const float* glb = (const float*)d_in[6];
    const float* pW  = (const float*)d_in[7];
    const float* pb  = (const float*)d_in[8];
    const float* mW  = (const float*)d_in[9];
    const float* mb  = (const float*)d_in[10];
    const float* slg = (const float*)d_in[11];
    const float* slb = (const float*)d_in[12];
    float* out = (float*)d_out;

    float *b0, *b1, *b2, *b3;
    cudaGetSymbolAddress((void**)&b0, g_buf0);
    cudaGetSymbolAddress((void**)&b1, g_buf1);
    cudaGetSymbolAddress((void**)&b2, g_buf2);
    cudaGetSymbolAddress((void**)&b3, g_buf3);

    // G jobs (GCN branch)
    GJob G0 = { x,  nullptr, gb,          nullptr, nullptr, nullptr, b0, 0, 1, M_PLAIN, D, 0 };
    GJob G1 = { b1, nullptr, gb + D,      nullptr, nullptr, nullptr, b0, 1, 1, M_PLAIN, D, 0 };
    GJob G2 = { b1, nullptr, gb + 2 * D,  nullptr, nullptr, nullptr, b0, 2, 1, M_PLAIN, D, 0 };
    // S jobs (SAGE branch, pool fused as chunk 1)
    GJob S0 = { x,  nullptr, pb,          nullptr, nullptr, nullptr, b2, 3, 1, M_RELU, D, 0 };
    GJob S1 = { x,  b2,      mb,          nullptr, nullptr, nullptr, b3, 4, 2, M_RELU, D, 0 };
    GJob S2 = { b3, b3,      mb + D,      b3, slg, slb,               b2, 6, 2, M_LN,   D, 0 };
    GJob S3 = { b2, b2,      mb + 2 * D,  b2, slg + D, slb + D,       out, 8, 2, M_LN, 2 * D, D };
    // P jobs
    PJob P0 = { b0, b0, glg,         glb,         b1,  D,     0 };
    PJob P1 = { b0, b1, glg + D,     glb + D,     b1,  D,     0 };
    PJob P2 = { b0, b1, glg + 2 * D, glb + 2 * D, out, 2 * D, 0 };

    prep_all_kernel<<<10 + N_NODES / 256, 256>>>(nei, nbc, gW, pW, mW);

    k_g2<<<2 * GB, 256, SMEM_TOTAL>>>(G0, S0);       // step1: G0 | S0
    k_gp<<<GB + PB, 256, SMEM_TOTAL>>>(S1, P0);      // step2: S1 | P0
    k_g2<<<2 * GB, 256, SMEM_TOTAL>>>(G1, S2);       // step3: G1 | S2
    k_gp<<<GB + PB, 256, SMEM_TOTAL>>>(S3, P1);      // step4: S3 | P1
    k_g1<<<GB, 256, SMEM_TOTAL>>>(G2);               // step5: G2
    k_p<<<PB, 256>>>(P2);                            // step6: P2
}

// round 10
// speedup vs baseline: 1.0439x; 1.0439x over previous
#include <cuda_runtime.h>
#include <cuda_bf16.h>
#include <cstdint>

#define N_NODES 8192
#define D 128
#define KNBR 8
#define LN_EPS 1e-5f

#define M_PLAIN 0
#define M_RELU  1
#define M_LN    2

#define MTILE 64
#define THREADS 512
// SMEM (bytes): Ah[64x128 bf16]=16K @0, Al=16K, Wh[128x128 bf16]=32K, Wl=32K
#define OFF_AL 16384
#define OFF_WH 32768
#define OFF_WL 65536
#define SMEM_TOTAL 98304
#define WTILE_BYTES 32768   // one pre-split W chunk [128 n][128 k] bf16

// ---------------- scratch (device globals: no allocation allowed) ----------
__device__ float g_buf0[N_NODES * D];
__device__ float g_buf1[N_NODES * D];
__device__ float g_buf2[N_NODES * D];
__device__ float g_buf3[N_NODES * D];
__device__ float g_dinv[N_NODES];
__device__ int   g_kcnt[N_NODES];
__device__ __align__(16) int g_gn[N_NODES * KNBR];      // gcn kept list, pad=i
__device__ __align__(16) int g_pooln[N_NODES * KNBR];   // pool list, pad=first
__device__ float g_pmul[N_NODES];                       // 0 if leaf else 1
// pre-split, pre-swizzled weights: 10 chunks of [128 rows x 128 cols] bf16
__device__ __align__(16) unsigned char g_wh[10 * WTILE_BYTES];
__device__ __align__(16) unsigned char g_wl[10 * WTILE_BYTES];

// ---------------- job descriptors -------------------------------------------
struct GJob {
    const float* A1; const float* psrc;
    const float* bias; const float* res; const float* lng; const float* lnb;
    float* out;
    int wchunk, nchunks, mode, ostride, ooff;
};
struct PJob {
    const float* nxt; const float* res; const float* lng; const float* lnb;
    float* out;
    int ostride, ooff;
};

// ---------------- helpers ---------------------------------------------------
__device__ __forceinline__ uint32_t smem_u32(const void* p) {
    uint32_t a;
    asm("{ .reg .u64 t; cvta.to.shared.u64 t, %1; cvt.u32.u64 %0, t; }"
        : "=r"(a) : "l"(p));
    return a;
}
__device__ __forceinline__ void ldsm4(uint32_t addr, uint32_t* r) {
    asm volatile("ldmatrix.sync.aligned.m8n8.x4.shared.b16 {%0,%1,%2,%3}, [%4];"
                 : "=r"(r[0]), "=r"(r[1]), "=r"(r[2]), "=r"(r[3]) : "r"(addr));
}
__device__ __forceinline__ void mma_bf16(float* d, const uint32_t* a,
                                         uint32_t b0, uint32_t b1) {
    asm volatile(
        "mma.sync.aligned.m16n8k16.row.col.f32.bf16.bf16.f32 "
        "{%0,%1,%2,%3}, {%4,%5,%6,%7}, {%8,%9}, {%0,%1,%2,%3};"
        : "+f"(d[0]), "+f"(d[1]), "+f"(d[2]), "+f"(d[3])
        : "r"(a[0]), "r"(a[1]), "r"(a[2]), "r"(a[3]), "r"(b0), "r"(b1));
}
__device__ __forceinline__ void cp_async16(uint32_t saddr, const void* g) {
    asm volatile("cp.async.cg.shared.global [%0], [%1], 16;"
                 :: "r"(saddr), "l"(g));
}
#define CP_COMMIT() asm volatile("cp.async.commit_group;")
#define CP_WAIT0()  asm volatile("cp.async.wait_group 0;" ::: "memory")

static __device__ __forceinline__ uint32_t bf2u(__nv_bfloat162 v) {
    return *reinterpret_cast<uint32_t*>(&v);
}
// pack 8 consecutive floats -> hi uint4 / lo uint4 (bf16 pairs)
__device__ __forceinline__ void split8(const float* f, uint4& hi, uint4& lo) {
    __nv_bfloat16 h[8];
    float l[8];
#pragma unroll
    for (int e = 0; e < 8; ++e) {
        h[e] = __float2bfloat16(f[e]);
        l[e] = f[e] - __bfloat162float(h[e]);
    }
    hi.x = bf2u(__halves2bfloat162(h[0], h[1]));
    hi.y = bf2u(__halves2bfloat162(h[2], h[3]));
    hi.z = bf2u(__halves2bfloat162(h[4], h[5]));
    hi.w = bf2u(__halves2bfloat162(h[6], h[7]));
    lo.x = bf2u(__floats2bfloat162_rn(l[0], l[1]));
    lo.y = bf2u(__floats2bfloat162_rn(l[2], l[3]));
    lo.z = bf2u(__floats2bfloat162_rn(l[4], l[5]));
    lo.w = bf2u(__floats2bfloat162_rn(l[6], l[7]));
}

// ---------------- prep: blocks 0-9 split W, blocks 10-41 graph tables ------
__global__ void prep_all_kernel(const int* __restrict__ neigh,
                                const int* __restrict__ nbrc,
                                const float* __restrict__ gW,
                                const float* __restrict__ pW,
                                const float* __restrict__ mW) {
    int c = blockIdx.x, tid = threadIdx.x;
    if (c >= 10) {
        int i = (c - 10) * 256 + tid;
        int cnt = nbrc[i];
        cnt = cnt > KNBR ? KNBR : (cnt < 0 ? 0 : cnt);
        int first = cnt > 0 ? neigh[i * KNBR] : 0;
#pragma unroll
        for (int k = 0; k < KNBR; ++k)
            g_pooln[i * KNBR + k] = k < cnt ? neigh[i * KNBR + k] : first;
        g_pmul[i] = cnt > 0 ? 1.f : 0.f;
        int kept[KNBR];
        int kc = 0;
        for (int k = 0; k < cnt; ++k) {
            int nb = neigh[i * KNBR + k];
            if (nb == i) continue;
            bool dup = false;
            for (int t = 0; t < kc; ++t) if (kept[t] == nb) dup = true;
            if (!dup) kept[kc++] = nb;
        }
#pragma unroll
        for (int k = 0; k < KNBR; ++k)
            g_gn[i * KNBR + k] = k < kc ? kept[k] : i;
        g_kcnt[i] = kc;
        g_dinv[i] = rsqrtf((float)(kc + 1));
        return;
    }
    const float* src;
    int stride, coloff;
    if (c < 3)       { src = gW + c * 16384; stride = 128; coloff = 0; }
    else if (c == 3) { src = pW;             stride = 128; coloff = 0; }
    else { int l = (c - 4) >> 1, h = (c - 4) & 1;
           src = mW + l * 32768; stride = 256; coloff = h * 128; }
    unsigned char* wh = g_wh + c * WTILE_BYTES;
    unsigned char* wl = g_wl + c * WTILE_BYTES;
    for (int i = tid; i < 2048; i += 256) {       // 16B chunks
        int n = i >> 4, ch = i & 15;
        float f[8];
#pragma unroll
        for (int e = 0; e < 8; ++e) f[e] = src[n * stride + coloff + ch * 8 + e];
        uint4 hi, lo;
        split8(f, hi, lo);
        uint32_t off = (uint32_t)n * 256 + ((uint32_t)(ch ^ (n & 7)) << 4);
        *(uint4*)(wh + off) = hi;
        *(uint4*)(wl + off) = lo;
    }
}

// ---------------- GEMM body: out = [A1 | pool(psrc)] @ W^T + b -------------
// hi/lo split: D = Ah@Wh + Ah@Wl + Al@Wh. 16 warps, warp tile 16x32.
__device__ void gemm_body(const GJob& J, int bid, char* smem_raw) {
    const uint32_t sbase = smem_u32(smem_raw);
    const int tid = threadIdx.x, wid = tid >> 5, lane = tid & 31;
    const int wm = wid & 3, wn = wid >> 2;   // rows wm*16..+15, cols wn*32..+31
    const int m0 = bid * MTILE;

    float acc[4][4];
#pragma unroll
    for (int j = 0; j < 4; ++j)
#pragma unroll
        for (int r = 0; r < 4; ++r) acc[j][r] = 0.f;

    const int lrow = lane & 15, lhalf = lane >> 4;
    const int rowA  = wm * 16 + lrow;
    const int rowB0 = wn * 32 + lrow, rowB1 = rowB0 + 16;

    for (int c = 0; c < J.nchunks; ++c) {
        if (c) __syncthreads();
        // W: cp.async first so its latency hides behind A conversion
        {
            const unsigned char* wh = g_wh + (J.wchunk + c) * WTILE_BYTES;
            const unsigned char* wl = g_wl + (J.wchunk + c) * WTILE_BYTES;
#pragma unroll
            for (int i = 0; i < 4; ++i) {
                int t = tid + i * THREADS;
                cp_async16(sbase + OFF_WH + t * 16, wh + t * 16);
                cp_async16(sbase + OFF_WL + t * 16, wl + t * 16);
            }
            CP_COMMIT();
        }
        if (c == 0) {
            for (int i = tid; i < 1024; i += THREADS) {
                int r = i >> 4, ch = i & 15;
                float f[8];
                float4 f0 = *(const float4*)&J.A1[(m0 + r) * D + ch * 8];
                float4 f1 = *(const float4*)&J.A1[(m0 + r) * D + ch * 8 + 4];
                f[0] = f0.x; f[1] = f0.y; f[2] = f0.z; f[3] = f0.w;
                f[4] = f1.x; f[5] = f1.y; f[6] = f1.z; f[7] = f1.w;
                uint4 hi, lo;
                split8(f, hi, lo);
                uint32_t off = (uint32_t)r * 256 + ((uint32_t)(ch ^ (r & 7)) << 4);
                *(uint4*)(smem_raw + off) = hi;
                *(uint4*)(smem_raw + OFF_AL + off) = lo;
            }
        } else {
            // fused max-pool gather: A2[r] = pmul * max over 8 padded nbrs
            for (int i = tid; i < 1024; i += THREADS) {
                int r = i >> 4, ch = i & 15;
                int node = m0 + r;
                const int4* nl = (const int4*)(g_pooln + node * KNBR);
                int4 na = nl[0], nb = nl[1];
                float pm = g_pmul[node];
                const float* p = J.psrc + (size_t)ch * 8;
                float4 m0v = *(const float4*)&p[(size_t)na.x * D];
                float4 m1v = *(const float4*)&p[(size_t)na.x * D + 4];
                int idx[7] = { na.y, na.z, na.w, nb.x, nb.y, nb.z, nb.w };
#pragma unroll
                for (int t = 0; t < 7; ++t) {
                    float4 r0 = *(const float4*)&p[(size_t)idx[t] * D];
                    float4 r1 = *(const float4*)&p[(size_t)idx[t] * D + 4];
                    m0v.x = fmaxf(m0v.x, r0.x); m0v.y = fmaxf(m0v.y, r0.y);
                    m0v.z = fmaxf(m0v.z, r0.z); m0v.w = fmaxf(m0v.w, r0.w);
                    m1v.x = fmaxf(m1v.x, r1.x); m1v.y = fmaxf(m1v.y, r1.y);
                    m1v.z = fmaxf(m1v.z, r1.z); m1v.w = fmaxf(m1v.w, r1.w);
                }
                float f[8];
                f[0] = pm * m0v.x; f[1] = pm * m0v.y;
                f[2] = pm * m0v.z; f[3] = pm * m0v.w;
                f[4] = pm * m1v.x; f[5] = pm * m1v.y;
                f[6] = pm * m1v.z; f[7] = pm * m1v.w;
                uint4 hi, lo;
                split8(f, hi, lo);
                uint32_t off = (uint32_t)r * 256 + ((uint32_t)(ch ^ (r & 7)) << 4);
                *(uint4*)(smem_raw + off) = hi;
                *(uint4*)(smem_raw + OFF_AL + off) = lo;
            }
        }
        CP_WAIT0();
        __syncthreads();

#pragma unroll
        for (int pass = 0; pass < 3; ++pass) {
            const uint32_t aB = sbase + (pass < 2 ? 0 : OFF_AL);
            const uint32_t wB = sbase + (pass == 1 ? OFF_WL : OFF_WH);
#pragma unroll
            for (int ks = 0; ks < 8; ++ks) {
                const int ch = ks * 2 + lhalf;
                uint32_t a[4], b0[4], b1[4];
                ldsm4(aB + rowA * 256 + ((uint32_t)(ch ^ (rowA & 7)) << 4), a);
                ldsm4(wB + rowB0 * 256 + ((uint32_t)(ch ^ (rowB0 & 7)) << 4), b0);
                ldsm4(wB + rowB1 * 256 + ((uint32_t)(ch ^ (rowB1 & 7)) << 4), b1);
                mma_bf16(acc[0], a, b0[0], b0[2]);
                mma_bf16(acc[1], a, b0[1], b0[3]);
                mma_bf16(acc[2], a, b1[0], b1[2]);
                mma_bf16(acc[3], a, b1[1], b1[3]);
            }
        }
    }

    const int frow = lane >> 2, fcol = 2 * (lane & 3);

    if (J.mode != M_LN) {
#pragma unroll
        for (int j = 0; j < 4; ++j) {
            int ncol = wn * 32 + j * 8 + fcol;
            float2 bj = *(const float2*)&J.bias[ncol];
            int m = m0 + wm * 16 + frow;
            float2 v0 = make_float2(acc[j][0] + bj.x, acc[j][1] + bj.y);
            float2 v1 = make_float2(acc[j][2] + bj.x, acc[j][3] + bj.y);
            if (J.mode == M_RELU) {
                v0.x = fmaxf(v0.x, 0.f); v0.y = fmaxf(v0.y, 0.f);
                v1.x = fmaxf(v1.x, 0.f); v1.y = fmaxf(v1.y, 0.f);
            }
            *(float2*)&J.out[m * J.ostride + J.ooff + ncol] = v0;
            *(float2*)&J.out[(m + 8) * J.ostride + J.ooff + ncol] = v1;
        }
        return;
    }

    // LN: relu(C+b) -> SMEM [64][132], then per-row LayerNorm with residual
    float* sC = (float*)smem_raw;
    __syncthreads();
#pragma unroll
    for (int j = 0; j < 4; ++j) {
        int ncol = wn * 32 + j * 8 + fcol;
        float2 bj = *(const float2*)&J.bias[ncol];
        int r = wm * 16 + frow;
        sC[r * 132 + ncol]           = fmaxf(acc[j][0] + bj.x, 0.f);
        sC[r * 132 + ncol + 1]       = fmaxf(acc[j][1] + bj.y, 0.f);
        sC[(r + 8) * 132 + ncol]     = fmaxf(acc[j][2] + bj.x, 0.f);
        sC[(r + 8) * 132 + ncol + 1] = fmaxf(acc[j][3] + bj.y, 0.f);
    }
    __syncthreads();

    {
        const int row = tid >> 3, q = tid & 7;     // 8 threads per row, 64 rows
        const int m = m0 + row;
        float v[16];
        float s = 0.f, ss = 0.f;
#pragma unroll
        for (int t = 0; t < 4; ++t) {
            int col = q * 16 + t * 4;
            float4 cv = *(float4*)&sC[row * 132 + col];
            float4 rv = *(const float4*)&J.res[m * D + col];
            v[4 * t + 0] = cv.x + rv.x; v[4 * t + 1] = cv.y + rv.y;
            v[4 * t + 2] = cv.z + rv.z; v[4 * t + 3] = cv.w + rv.w;
            s  += v[4 * t] + v[4 * t + 1] + v[4 * t + 2] + v[4 * t + 3];
            ss += v[4 * t] * v[4 * t] + v[4 * t + 1] * v[4 * t + 1] +
                  v[4 * t + 2] * v[4 * t + 2] + v[4 * t + 3] * v[4 * t + 3];
        }
#pragma unroll
        for (int off = 1; off < 8; off <<= 1) {
            s  += __shfl_xor_sync(0xffffffffu, s,  off);
            ss += __shfl_xor_sync(0xffffffffu, ss, off);
        }
        float mean = s * (1.0f / 128.0f);
        float rstd = rsqrtf(ss * (1.0f / 128.0f) - mean * mean + LN_EPS);
#pragma unroll
        for (int t = 0; t < 4; ++t) {
            int col = q * 16 + t * 4;
            float4 gj = *(const float4*)&J.lng[col];
            float4 oj = *(const float4*)&J.lnb[col];
            float4 o;
            o.x = (v[4 * t + 0] - mean) * rstd * gj.x + oj.x;
            o.y = (v[4 * t + 1] - mean) * rstd * gj.y + oj.y;
            o.z = (v[4 * t + 2] - mean) * rstd * gj.z + oj.z;
            o.w = (v[4 * t + 3] - mean) * rstd * gj.w + oj.w;
            *(float4*)&J.out[m * J.ostride + J.ooff + col] = o;
        }
    }
}

// ---------------- prop body: 64 nodes per block (16 warps x 4 nodes) -------
__device__ void prop_body(const PJob& P, int blk) {
    const int lane = threadIdx.x & 31, wid = threadIdx.x >> 5;
    const int base = blk * 64 + wid * 4;
    for (int t = 0; t < 4; ++t) {
        const int i = base + t;
        const float di = g_dinv[i];
        float4 s4 = ((const float4*)(P.nxt + (size_t)i * D))[lane];
        float4 acc = make_float4(di * s4.x, di * s4.y, di * s4.z, di * s4.w);
        const int kc = g_kcnt[i];
        const int* kn = g_gn + i * KNBR;
        for (int k = 0; k < kc; ++k) {
            int j = kn[k];
            float dj = g_dinv[j];
            float4 r = ((const float4*)(P.nxt + (size_t)j * D))[lane];
            acc.x += dj * r.x; acc.y += dj * r.y;
            acc.z += dj * r.z; acc.w += dj * r.w;
        }
        float4 rr = ((const float4*)(P.res + (size_t)i * D))[lane];
        float4 v;
        v.x = fmaxf(di * acc.x, 0.f) + rr.x;
        v.y = fmaxf(di * acc.y, 0.f) + rr.y;
        v.z = fmaxf(di * acc.z, 0.f) + rr.z;
        v.w = fmaxf(di * acc.w, 0.f) + rr.w;
        float s  = v.x + v.y + v.z + v.w;
        float ss = v.x * v.x + v.y * v.y + v.z * v.z + v.w * v.w;
#pragma unroll
        for (int off = 16; off; off >>= 1) {
            s  += __shfl_xor_sync(0xffffffffu, s,  off);
            ss += __shfl_xor_sync(0xffffffffu, ss, off);
        }
        float mean = s * (1.0f / 128.0f);
        float rstd = rsqrtf(ss * (1.0f / 128.0f) - mean * mean + LN_EPS);
        float4 gj = ((const float4*)P.lng)[lane];
        float4 oj = ((const float4*)P.lnb)[lane];
        float4 o;
        o.x = (v.x - mean) * rstd * gj.x + oj.x;
        o.y = (v.y - mean) * rstd * gj.y + oj.y;
        o.z = (v.z - mean) * rstd * gj.z + oj.z;
        o.w = (v.w - mean) * rstd * gj.w + oj.w;
        *(float4*)&P.out[(size_t)i * P.ostride + P.ooff + 4 * lane] = o;
    }
}

#define GB (N_NODES / MTILE)    // 128 gemm tiles
#define PB (N_NODES / 64)       // 128 prop blocks

// ---------------- named step kernels ----------------------------------------
__global__ __launch_bounds__(THREADS, 2) void k_g2(GJob g0, GJob g1) {
    extern __shared__ __align__(256) char smem_raw[];
    int b = blockIdx.x;
    if (b < GB) gemm_body(g0, b, smem_raw);
    else        gemm_body(g1, b - GB, smem_raw);
}
__global__ __launch_bounds__(THREADS, 2) void k_gp(GJob g, PJob p) {
    extern __shared__ __align__(256) char smem_raw[];
    int b = blockIdx.x;
    if (b < GB) gemm_body(g, b, smem_raw);
    else        prop_body(p, b - GB);
}
__global__ __launch_bounds__(THREADS, 2) void k_g1(GJob g) {
    extern __shared__ __align__(256) char smem_raw[];
    gemm_body(g, blockIdx.x, smem_raw);
}
__global__ __launch_bounds__(THREADS) void k_p(PJob p) {
    prop_body(p, blockIdx.x);
}

// ---------------- driver ----------------------------------------------------
extern "C" void kernel_launch(void* const* d_in, const int* in_sizes, int n_in,
                              void* d_out, int out_size) {
    const float* x   = (const float*)d_in[0];
    const int*   nei = (const int*)  d_in[1];
    const int*   nbc = (const int*)  d_in[2];
    const float* gW  = (const float*)d_in[3];
    const float* gb  = (const float*)d_in[4];
    const float* glg = (const float*)d_in[5];
    const float* glb = (const float*)d_in[6];
    const float* pW  = (const float*)d_in[7];
    const float* pb  = (const float*)d_in[8];
    const float* mW  = (const float*)d_in[9];
    const float* mb  = (const float*)d_in[10];
    const float* slg = (const float*)d_in[11];
    const float* slb = (const float*)d_in[12];
    float* out = (float*)d_out;

    float *b0, *b1, *b2, *b3;
    cudaGetSymbolAddress((void**)&b0, g_buf0);
    cudaGetSymbolAddress((void**)&b1, g_buf1);
    cudaGetSymbolAddress((void**)&b2, g_buf2);
    cudaGetSymbolAddress((void**)&b3, g_buf3);

    cudaFuncSetAttribute(k_g2, cudaFuncAttributeMaxDynamicSharedMemorySize, SMEM_TOTAL);
    cudaFuncSetAttribute(k_gp, cudaFuncAttributeMaxDynamicSharedMemorySize, SMEM_TOTAL);
    cudaFuncSetAttribute(k_g1, cudaFuncAttributeMaxDynamicSharedMemorySize, SMEM_TOTAL);

    // G jobs (GCN branch)
    GJob G0 = { x,  nullptr, gb,          nullptr, nullptr, nullptr, b0, 0, 1, M_PLAIN, D, 0 };
    GJob G1 = { b1, nullptr, gb + D,      nullptr, nullptr, nullptr, b0, 1, 1, M_PLAIN, D, 0 };
    GJob G2 = { b1, nullptr, gb + 2 * D,  nullptr, nullptr, nullptr, b0, 2, 1, M_PLAIN, D, 0 };
    // S jobs (SAGE branch, pool fused as chunk 1)
    GJob S0 = { x,  nullptr, pb,          nullptr, nullptr, nullptr, b2, 3, 1, M_RELU, D, 0 };
    GJob S1 = { x,  b2,      mb,          nullptr, nullptr, nullptr, b3, 4, 2, M_RELU, D, 0 };
    GJob S2 = { b3, b3,      mb + D,      b3, slg, slb,               b2, 6, 2, M_LN,   D, 0 };
    GJob S3 = { b2, b2,      mb + 2 * D,  b2, slg + D, slb + D,       out, 8, 2, M_LN, 2 * D, D };
    // P jobs
    PJob P0 = { b0, b0, glg,         glb,         b1,  D,     0 };
    PJob P1 = { b0, b1, glg + D,     glb + D,     b1,  D,     0 };
    PJob P2 = { b0, b1, glg + 2 * D, glb + 2 * D, out, 2 * D, 0 };

    prep_all_kernel<<<10 + N_NODES / 256, 256>>>(nei, nbc, gW, pW, mW);

    k_g2<<<2 * GB, THREADS, SMEM_TOTAL>>>(G0, S0);       // step1: G0 | S0
    k_gp<<<GB + PB, THREADS, SMEM_TOTAL>>>(S1, P0);      // step2: S1 | P0
    k_g2<<<2 * GB, THREADS, SMEM_TOTAL>>>(G1, S2);       // step3: G1 | S2
    k_gp<<<GB + PB, THREADS, SMEM_TOTAL>>>(S3, P1);      // step4: S3 | P1
    k_g1<<<GB, THREADS, SMEM_TOTAL>>>(G2);               // step5: G2
    k_p<<<PB, THREADS>>>(P2);                            // step6: P2
}

// round 11
// speedup vs baseline: 1.3287x; 1.2729x over previous
#include <cuda_runtime.h>
#include <cuda_bf16.h>
#include <cstdint>

#define N_NODES 8192
#define D 128
#define KNBR 8
#define LN_EPS 1e-5f

#define M_PLAIN 0
#define M_RELU  1
#define M_LN    2

#define MTILE 64
#define THREADS 256
// SMEM (bytes): Ah[64x128 bf16]=16K @0, Al @16384, Wh @32768 (32K), Wl @65536
#define OFF_AL 16384
#define OFF_WH 32768
#define OFF_WL 65536
#define SMEM_TOTAL 98304
#define WTILE_BYTES 32768
#define ROWB 256               // bytes per activation row per plane (128 bf16)

// ---------------- device globals (no allocation allowed) -------------------
// activation planes: hi/lo bf16, swizzled rows (chunk ch at ((ch^(r&7))<<4))
__device__ __align__(16) unsigned char g_xh[N_NODES * ROWB];
__device__ __align__(16) unsigned char g_xl[N_NODES * ROWB];
__device__ __align__(16) unsigned char g_h0[N_NODES * ROWB];
__device__ __align__(16) unsigned char g_l0[N_NODES * ROWB];
__device__ __align__(16) unsigned char g_h1[N_NODES * ROWB];
__device__ __align__(16) unsigned char g_l1[N_NODES * ROWB];
__device__ __align__(16) unsigned char g_h2[N_NODES * ROWB];
__device__ __align__(16) unsigned char g_l2[N_NODES * ROWB];
__device__ __align__(16) unsigned char g_h3[N_NODES * ROWB];
__device__ __align__(16) unsigned char g_l3[N_NODES * ROWB];
__device__ float g_dinv[N_NODES];
__device__ int   g_kcnt[N_NODES];
__device__ __align__(16) int g_gn[N_NODES * KNBR];      // gcn kept list, pad=i
__device__ __align__(16) int g_pooln[N_NODES * KNBR];   // pool list, pad=first
__device__ float g_pmul[N_NODES];                       // 0 if leaf else 1
// pre-split, pre-swizzled weights: 10 chunks of [128 n][128 k] bf16
__device__ __align__(16) unsigned char g_wh[10 * WTILE_BYTES];
__device__ __align__(16) unsigned char g_wl[10 * WTILE_BYTES];

// ---------------- job descriptors -------------------------------------------
struct GJob {
    const unsigned char *ah, *al;     // A chunk-0 planes
    const unsigned char *ph, *pl;     // pool source planes (chunk 1)
    const unsigned char *rh, *rl;     // residual planes (LN)
    const float *bias, *lng, *lnb;
    float* outf;                      // fp32 out (or null)
    unsigned char *oh, *ol;           // hi/lo out (if outf null)
    int wchunk, nchunks, mode, ostride, ooff;
};
struct PJob {
    const unsigned char *nh, *nl;     // nxt planes
    const unsigned char *rh, *rl;     // res planes
    const float *lng, *lnb;
    float* outf;
    unsigned char *oh, *ol;
    int ostride, ooff;
};

// ---------------- helpers ---------------------------------------------------
__device__ __forceinline__ uint32_t smem_u32(const void* p) {
    uint32_t a;
    asm("{ .reg .u64 t; cvta.to.shared.u64 t, %1; cvt.u32.u64 %0, t; }"
        : "=r"(a) : "l"(p));
    return a;
}
__device__ __forceinline__ void ldsm4(uint32_t addr, uint32_t* r) {
    asm volatile("ldmatrix.sync.aligned.m8n8.x4.shared.b16 {%0,%1,%2,%3}, [%4];"
                 : "=r"(r[0]), "=r"(r[1]), "=r"(r[2]), "=r"(r[3]) : "r"(addr));
}
__device__ __forceinline__ void mma_bf16(float* d, const uint32_t* a,
                                         uint32_t b0, uint32_t b1) {
    asm volatile(
        "mma.sync.aligned.m16n8k16.row.col.f32.bf16.bf16.f32 "
        "{%0,%1,%2,%3}, {%4,%5,%6,%7}, {%8,%9}, {%0,%1,%2,%3};"
        : "+f"(d[0]), "+f"(d[1]), "+f"(d[2]), "+f"(d[3])
        : "r"(a[0]), "r"(a[1]), "r"(a[2]), "r"(a[3]), "r"(b0), "r"(b1));
}
__device__ __forceinline__ void bulk_g2s(uint32_t dst, const void* src,
                                         uint32_t bytes, uint32_t mbar) {
    asm volatile(
        "cp.async.bulk.shared::cluster.global.mbarrier::complete_tx::bytes "
        "[%0], [%1], %2, [%3];"
        :: "r"(dst), "l"(src), "r"(bytes), "r"(mbar) : "memory");
}
__device__ __forceinline__ void mbar_init(uint32_t a, uint32_t cnt) {
    asm volatile("mbarrier.init.shared.b64 [%0], %1;" :: "r"(a), "r"(cnt) : "memory");
}
__device__ __forceinline__ void mbar_expect_tx(uint32_t a, uint32_t tx) {
    asm volatile("mbarrier.arrive.expect_tx.shared.b64 _, [%0], %1;"
                 :: "r"(a), "r"(tx) : "memory");
}
__device__ __forceinline__ void mbar_wait(uint32_t a, uint32_t parity) {
    asm volatile(
        "{\n\t.reg .pred P;\n\t"
        "WL_%=:\n\t"
        "mbarrier.try_wait.parity.acquire.cta.shared::cta.b64 P, [%0], %1, 0x989680;\n\t"
        "@P bra.uni WD_%=;\n\t"
        "bra.uni WL_%=;\n\t"
        "WD_%=:\n\t}"
        :: "r"(a), "r"(parity) : "memory");
}
static __device__ __forceinline__ uint32_t bf2u(__nv_bfloat162 v) {
    return *reinterpret_cast<uint32_t*>(&v);
}
// pack 8 floats -> hi uint4 / lo uint4 (bf16 pairs)
__device__ __forceinline__ void split8(const float* f, uint4& hi, uint4& lo) {
    __nv_bfloat16 h[8];
    float l[8];
#pragma unroll
    for (int e = 0; e < 8; ++e) {
        h[e] = __float2bfloat16(f[e]);
        l[e] = f[e] - __bfloat162float(h[e]);
    }
    hi.x = bf2u(__halves2bfloat162(h[0], h[1]));
    hi.y = bf2u(__halves2bfloat162(h[2], h[3]));
    hi.z = bf2u(__halves2bfloat162(h[4], h[5]));
    hi.w = bf2u(__halves2bfloat162(h[6], h[7]));
    lo.x = bf2u(__floats2bfloat162_rn(l[0], l[1]));
    lo.y = bf2u(__floats2bfloat162_rn(l[2], l[3]));
    lo.z = bf2u(__floats2bfloat162_rn(l[4], l[5]));
    lo.w = bf2u(__floats2bfloat162_rn(l[6], l[7]));
}
// reconstruct 8 fp32 from one swizzled 16B hi + 16B lo chunk
__device__ __forceinline__ void rec8(const unsigned char* hp,
                                     const unsigned char* lp,
                                     uint32_t off, float* v) {
    uint4 h = *(const uint4*)(hp + off);
    uint4 l = *(const uint4*)(lp + off);
    float2 p, q;
    p = __bfloat1622float2(*(const __nv_bfloat162*)&h.x);
    q = __bfloat1622float2(*(const __nv_bfloat162*)&l.x);
    v[0] = p.x + q.x; v[1] = p.y + q.y;
    p = __bfloat1622float2(*(const __nv_bfloat162*)&h.y);
    q = __bfloat1622float2(*(const __nv_bfloat162*)&l.y);
    v[2] = p.x + q.x; v[3] = p.y + q.y;
    p = __bfloat1622float2(*(const __nv_bfloat162*)&h.z);
    q = __bfloat1622float2(*(const __nv_bfloat162*)&l.z);
    v[4] = p.x + q.x; v[5] = p.y + q.y;
    p = __bfloat1622float2(*(const __nv_bfloat162*)&h.w);
    q = __bfloat1622float2(*(const __nv_bfloat162*)&l.w);
    v[6] = p.x + q.x; v[7] = p.y + q.y;
}
__device__ __forceinline__ uint32_t swz(int r, int ch) {
    return (uint32_t)r * ROWB + ((uint32_t)(ch ^ (r & 7)) << 4);
}

// ---------------- prep: W split (0-9), graph (10-41), x convert (42-105) ---
__global__ void prep_all_kernel(const int* __restrict__ neigh,
                                const int* __restrict__ nbrc,
                                const float* __restrict__ gW,
                                const float* __restrict__ pW,
                                const float* __restrict__ mW,
                                const float* __restrict__ x) {
    int c = blockIdx.x, tid = threadIdx.x;
    if (c >= 42) {                       // x -> hi/lo swizzled planes
        int base = (c - 42) * 128;
        for (int it = 0; it < 8; ++it) {
            int idx = tid + it * 256;
            int r = base + (idx >> 4), ch = idx & 15;
            float f[8];
            float4 f0 = *(const float4*)&x[r * D + ch * 8];
            float4 f1 = *(const float4*)&x[r * D + ch * 8 + 4];
            f[0]=f0.x; f[1]=f0.y; f[2]=f0.z; f[3]=f0.w;
            f[4]=f1.x; f[5]=f1.y; f[6]=f1.z; f[7]=f1.w;
            uint4 hi, lo;
            split8(f, hi, lo);
            uint32_t off = swz(r, ch);
            *(uint4*)(g_xh + off) = hi;
            *(uint4*)(g_xl + off) = lo;
        }
        return;
    }
    if (c >= 10) {                       // graph tables
        int i = (c - 10) * 256 + tid;
        int cnt = nbrc[i];
        cnt = cnt > KNBR ? KNBR : (cnt < 0 ? 0 : cnt);
        int first = cnt > 0 ? neigh[i * KNBR] : 0;
#pragma unroll
        for (int k = 0; k < KNBR; ++k)
            g_pooln[i * KNBR + k] = k < cnt ? neigh[i * KNBR + k] : first;
        g_pmul[i] = cnt > 0 ? 1.f : 0.f;
        int kept[KNBR];
        int kc = 0;
        for (int k = 0; k < cnt; ++k) {
            int nb = neigh[i * KNBR + k];
            if (nb == i) continue;
            bool dup = false;
            for (int t = 0; t < kc; ++t) if (kept[t] == nb) dup = true;
            if (!dup) kept[kc++] = nb;
        }
#pragma unroll
        for (int k = 0; k < KNBR; ++k)
            g_gn[i * KNBR + k] = k < kc ? kept[k] : i;
        g_kcnt[i] = kc;
        g_dinv[i] = rsqrtf((float)(kc + 1));
        return;
    }
    // W chunks
    const float* src;
    int stride, coloff;
    if (c < 3)       { src = gW + c * 16384; stride = 128; coloff = 0; }
    else if (c == 3) { src = pW;             stride = 128; coloff = 0; }
    else { int l = (c - 4) >> 1, h = (c - 4) & 1;
           src = mW + l * 32768; stride = 256; coloff = h * 128; }
    unsigned char* wh = g_wh + c * WTILE_BYTES;
    unsigned char* wl = g_wl + c * WTILE_BYTES;
    for (int i = tid; i < 2048; i += 256) {
        int n = i >> 4, ch = i & 15;
        float f[8];
#pragma unroll
        for (int e = 0; e < 8; ++e) f[e] = src[n * stride + coloff + ch * 8 + e];
        uint4 hi, lo;
        split8(f, hi, lo);
        uint32_t off = swz(n, ch);
        *(uint4*)(wh + off) = hi;
        *(uint4*)(wl + off) = lo;
    }
}

// ---------------- GEMM body: out = [A | pool(psrc)] @ W^T + b --------------
// hi/lo split: D = Ah@Wh + Ah@Wl + Al@Wh (fp32 accum). 8 warps, 32x32 tiles.
__device__ void gemm_body(const GJob& J, int bid, char* smem_raw) {
    __shared__ __align__(8) uint64_t s_mbar;
    const uint32_t sbase = smem_u32(smem_raw);
    const uint32_t mbar = smem_u32(&s_mbar);
    const int tid = threadIdx.x, wid = tid >> 5, lane = tid & 31;
    const int wm = wid & 1, wn = wid >> 1;
    const int m0 = bid * MTILE;

    if (tid == 0) mbar_init(mbar, 1);
    __syncthreads();

    float acc[2][4][4];
#pragma unroll
    for (int i = 0; i < 2; ++i)
#pragma unroll
        for (int j = 0; j < 4; ++j)
#pragma unroll
            for (int r = 0; r < 4; ++r) acc[i][j][r] = 0.f;

    const int lrow = lane & 15, lhalf = lane >> 4;
    const int rowA0 = wm * 32 + lrow, rowA1 = rowA0 + 16;
    const int rowB0 = wn * 32 + lrow, rowB1 = rowB0 + 16;

    for (int c = 0; c < J.nchunks; ++c) {
        if (c) __syncthreads();
        if (tid == 0) {
            uint32_t tx = 2 * WTILE_BYTES + (c == 0 ? 32768u : 0u);
            mbar_expect_tx(mbar, tx);
            const unsigned char* wh = g_wh + (J.wchunk + c) * WTILE_BYTES;
            const unsigned char* wl = g_wl + (J.wchunk + c) * WTILE_BYTES;
            bulk_g2s(sbase + OFF_WH, wh, WTILE_BYTES, mbar);
            bulk_g2s(sbase + OFF_WL, wl, WTILE_BYTES, mbar);
            if (c == 0) {
                bulk_g2s(sbase,          J.ah + (size_t)m0 * ROWB, 16384, mbar);
                bulk_g2s(sbase + OFF_AL, J.al + (size_t)m0 * ROWB, 16384, mbar);
            }
        }
        if (c == 1) {
            // fused max-pool gather into A smem (hi/lo, swizzled)
            for (int i = tid; i < 1024; i += THREADS) {
                int r = i >> 4, ch = i & 15;
                int node = m0 + r;
                const int4* nl = (const int4*)(g_pooln + node * KNBR);
                int4 na = nl[0], nb = nl[1];
                float pm = g_pmul[node];
                int idx[8] = { na.x, na.y, na.z, na.w, nb.x, nb.y, nb.z, nb.w };
                float mv[8], tv[8];
                rec8(J.ph, J.pl, swz(idx[0], ch), mv);
#pragma unroll
                for (int t = 1; t < 8; ++t) {
                    rec8(J.ph, J.pl, swz(idx[t], ch), tv);
#pragma unroll
                    for (int e = 0; e < 8; ++e) mv[e] = fmaxf(mv[e], tv[e]);
                }
#pragma unroll
                for (int e = 0; e < 8; ++e) mv[e] *= pm;
                uint4 hi, lo;
                split8(mv, hi, lo);
                uint32_t off = swz(r, ch);
                *(uint4*)(smem_raw + off) = hi;
                *(uint4*)(smem_raw + OFF_AL + off) = lo;
            }
        }
        __syncthreads();
        mbar_wait(mbar, c & 1);

#pragma unroll
        for (int pass = 0; pass < 3; ++pass) {
            const uint32_t aB = sbase + (pass < 2 ? 0 : OFF_AL);
            const uint32_t wB = sbase + (pass == 1 ? OFF_WL : OFF_WH);
#pragma unroll
            for (int ks = 0; ks < 8; ++ks) {
                const int ch = ks * 2 + lhalf;
                uint32_t a0[4], a1[4], b0[4], b1[4];
                ldsm4(aB + swz(rowA0, ch), a0);
                ldsm4(aB + swz(rowA1, ch), a1);
                ldsm4(wB + swz(rowB0, ch), b0);
                ldsm4(wB + swz(rowB1, ch), b1);
                mma_bf16(acc[0][0], a0, b0[0], b0[2]);
                mma_bf16(acc[0][1], a0, b0[1], b0[3]);
                mma_bf16(acc[0][2], a0, b1[0], b1[2]);
                mma_bf16(acc[0][3], a0, b1[1], b1[3]);
                mma_bf16(acc[1][0], a1, b0[0], b0[2]);
                mma_bf16(acc[1][1], a1, b0[1], b0[3]);
                mma_bf16(acc[1][2], a1, b1[0], b1[2]);
                mma_bf16(acc[1][3], a1, b1[1], b1[3]);
            }
        }
    }

    // ---- epilogue: fragments -> sC fp32 (bias [+relu]) -> per-row finish --
    const int frow = lane >> 2, fcol = 2 * (lane & 3);
    float* sC = (float*)smem_raw;                 // [64][132]
    __syncthreads();
#pragma unroll
    for (int i = 0; i < 2; ++i)
#pragma unroll
        for (int j = 0; j < 4; ++j) {
            int ncol = wn * 32 + j * 8 + fcol;
            float2 bj = *(const float2*)&J.bias[ncol];
            int r = wm * 32 + i * 16 + frow;
            float v0 = acc[i][j][0] + bj.x, v1 = acc[i][j][1] + bj.y;
            float v2 = acc[i][j][2] + bj.x, v3 = acc[i][j][3] + bj.y;
            if (J.mode != M_PLAIN) {
                v0 = fmaxf(v0, 0.f); v1 = fmaxf(v1, 0.f);
                v2 = fmaxf(v2, 0.f); v3 = fmaxf(v3, 0.f);
            }
            sC[r * 132 + ncol]           = v0;
            sC[r * 132 + ncol + 1]       = v1;
            sC[(r + 8) * 132 + ncol]     = v2;
            sC[(r + 8) * 132 + ncol + 1] = v3;
        }
    __syncthreads();

    {
        const int row = tid >> 2, q = tid & 3;     // 4 threads/row, 64 rows
        const int m = m0 + row;
        float v[32];
#pragma unroll
        for (int t = 0; t < 8; ++t)
            *(float4*)&v[4 * t] = *(float4*)&sC[row * 132 + q * 32 + 4 * t];

        if (J.mode == M_LN) {
            float r8[8];
#pragma unroll
            for (int cq = 0; cq < 4; ++cq) {
                rec8(J.rh, J.rl, swz(m, q * 4 + cq), r8);
#pragma unroll
                for (int e = 0; e < 8; ++e) v[8 * cq + e] += r8[e];
            }
            float s = 0.f, ss = 0.f;
#pragma unroll
            for (int e = 0; e < 32; ++e) { s += v[e]; ss += v[e] * v[e]; }
#pragma unroll
            for (int off = 1; off < 4; off <<= 1) {
                s  += __shfl_xor_sync(0xffffffffu, s,  off);
                ss += __shfl_xor_sync(0xffffffffu, ss, off);
            }
            float mean = s * (1.0f / 128.0f);
            float rstd = rsqrtf(ss * (1.0f / 128.0f) - mean * mean + LN_EPS);
#pragma unroll
            for (int t = 0; t < 8; ++t) {
                float4 gj = *(const float4*)&J.lng[q * 32 + 4 * t];
                float4 oj = *(const float4*)&J.lnb[q * 32 + 4 * t];
                v[4 * t + 0] = (v[4 * t + 0] - mean) * rstd * gj.x + oj.x;
                v[4 * t + 1] = (v[4 * t + 1] - mean) * rstd * gj.y + oj.y;
                v[4 * t + 2] = (v[4 * t + 2] - mean) * rstd * gj.z + oj.z;
                v[4 * t + 3] = (v[4 * t + 3] - mean) * rstd * gj.w + oj.w;
            }
        }
        if (J.outf) {
#pragma unroll
            for (int t = 0; t < 8; ++t)
                *(float4*)&J.outf[(size_t)m * J.ostride + J.ooff + q * 32 + 4 * t] =
                    *(float4*)&v[4 * t];
        } else {
#pragma unroll
            for (int cq = 0; cq < 4; ++cq) {
                uint4 hi, lo;
                split8(&v[8 * cq], hi, lo);
                uint32_t off = swz(m, q * 4 + cq);
                *(uint4*)(J.oh + off) = hi;
                *(uint4*)(J.ol + off) = lo;
            }
        }
    }
}

// ---------------- prop body: 64 nodes/block, 2 nodes/warp, 16-lane rows ----
__device__ void prop_body(const PJob& P, int blk) {
    const int lane = threadIdx.x & 31, wid = threadIdx.x >> 5;
    const int half = lane >> 4, ch = lane & 15;
    for (int t = 0; t < 4; ++t) {
        const int i = blk * 64 + t * 16 + wid * 2 + half;
        const float di = g_dinv[i];
        float a[8], acc[8];
        rec8(P.nh, P.nl, swz(i, ch), a);
#pragma unroll
        for (int e = 0; e < 8; ++e) acc[e] = di * a[e];
        const int kc = g_kcnt[i];
        const int* kn = g_gn + i * KNBR;
        for (int k = 0; k < kc; ++k) {
            int j = kn[k];
            float dj = g_dinv[j];
            rec8(P.nh, P.nl, swz(j, ch), a);
#pragma unroll
            for (int e = 0; e < 8; ++e) acc[e] += dj * a[e];
        }
        rec8(P.rh, P.rl, swz(i, ch), a);           // residual
        float v[8];
        float s = 0.f, ss = 0.f;
#pragma unroll
        for (int e = 0; e < 8; ++e) {
            v[e] = fmaxf(di * acc[e], 0.f) + a[e];
            s += v[e]; ss += v[e] * v[e];
        }
#pragma unroll
        for (int off = 1; off < 16; off <<= 1) {
            s  += __shfl_xor_sync(0xffffffffu, s,  off);
            ss += __shfl_xor_sync(0xffffffffu, ss, off);
        }
        float mean = s * (1.0f / 128.0f);
        float rstd = rsqrtf(ss * (1.0f / 128.0f) - mean * mean + LN_EPS);
        float4 g0 = *(const float4*)&P.lng[ch * 8];
        float4 g1 = *(const float4*)&P.lng[ch * 8 + 4];
        float4 o0 = *(const float4*)&P.lnb[ch * 8];
        float4 o1 = *(const float4*)&P.lnb[ch * 8 + 4];
        v[0] = (v[0] - mean) * rstd * g0.x + o0.x;
        v[1] = (v[1] - mean) * rstd * g0.y + o0.y;
        v[2] = (v[2] - mean) * rstd * g0.z + o0.z;
        v[3] = (v[3] - mean) * rstd * g0.w + o0.w;
        v[4] = (v[4] - mean) * rstd * g1.x + o1.x;
        v[5] = (v[5] - mean) * rstd * g1.y + o1.y;
        v[6] = (v[6] - mean) * rstd * g1.z + o1.z;
        v[7] = (v[7] - mean) * rstd * g1.w + o1.w;
        if (P.outf) {
            *(float4*)&P.outf[(size_t)i * P.ostride + P.ooff + ch * 8]     = *(float4*)&v[0];
            *(float4*)&P.outf[(size_t)i * P.ostride + P.ooff + ch * 8 + 4] = *(float4*)&v[4];
        } else {
            uint4 hi, lo;
            split8(v, hi, lo);
            uint32_t off = swz(i, ch);
            *(uint4*)(P.oh + off) = hi;
            *(uint4*)(P.ol + off) = lo;
        }
    }
}

#define GB (N_NODES / MTILE)    // 128 gemm tiles
#define PB (N_NODES / 64)       // 128 prop blocks

// ---------------- named step kernels ----------------------------------------
__global__ __launch_bounds__(THREADS, 2) void k_g2(GJob g0, GJob g1) {
    extern __shared__ __align__(256) char smem_raw[];
    int b = blockIdx.x;
    if (b < GB) gemm_body(g0, b, smem_raw);
    else        gemm_body(g1, b - GB, smem_raw);
}
__global__ __launch_bounds__(THREADS, 2) void k_gp(GJob g, PJob p) {
    extern __shared__ __align__(256) char smem_raw[];
    int b = blockIdx.x;
    if (b < GB) gemm_body(g, b, smem_raw);
    else        prop_body(p, b - GB);
}
__global__ __launch_bounds__(THREADS, 2) void k_g1(GJob g) {
    extern __shared__ __align__(256) char smem_raw[];
    gemm_body(g, blockIdx.x, smem_raw);
}
__global__ __launch_bounds__(THREADS) void k_p(PJob p) {
    prop_body(p, blockIdx.x);
}

// ---------------- driver ----------------------------------------------------
extern "C" void kernel_launch(void* const* d_in, const int* in_sizes, int n_in,
                              void* d_out, int out_size) {
    const float* x   = (const float*)d_in[0];
    const int*   nei = (const int*)  d_in[1];
    const int*   nbc = (const int*)  d_in[2];
    const float* gW  = (const float*)d_in[3];
    const float* gb  = (const float*)d_in[4];
    const float* glg = (const float*)d_in[5];
    const float* glb = (const float*)d_in[6];
    const float* pW  = (const float*)d_in[7];
    const float* pb  = (const float*)d_in[8];
    const float* mW  = (const float*)d_in[9];
    const float* mb  = (const float*)d_in[10];
    const float* slg = (const float*)d_in[11];
    const float* slb = (const float*)d_in[12];
    float* out = (float*)d_out;

    unsigned char *xh, *xl, *h0, *l0, *h1, *l1, *h2, *l2, *h3, *l3;
    cudaGetSymbolAddress((void**)&xh, g_xh);
    cudaGetSymbolAddress((void**)&xl, g_xl);
    cudaGetSymbolAddress((void**)&h0, g_h0);
    cudaGetSymbolAddress((void**)&l0, g_l0);
    cudaGetSymbolAddress((void**)&h1, g_h1);
    cudaGetSymbolAddress((void**)&l1, g_l1);
    cudaGetSymbolAddress((void**)&h2, g_h2);
    cudaGetSymbolAddress((void**)&l2, g_l2);
    cudaGetSymbolAddress((void**)&h3, g_h3);
    cudaGetSymbolAddress((void**)&l3, g_l3);

    cudaFuncSetAttribute(k_g2, cudaFuncAttributeMaxDynamicSharedMemorySize, SMEM_TOTAL);
    cudaFuncSetAttribute(k_gp, cudaFuncAttributeMaxDynamicSharedMemorySize, SMEM_TOTAL);
    cudaFuncSetAttribute(k_g1, cudaFuncAttributeMaxDynamicSharedMemorySize, SMEM_TOTAL);

    // G jobs (GCN): A-planes, w, PLAIN -> buf0 planes
    GJob G0 = { xh, xl, nullptr, nullptr, nullptr, nullptr,
                gb, nullptr, nullptr, nullptr, h0, l0, 0, 1, M_PLAIN, D, 0 };
    GJob G1 = { h1, l1, nullptr, nullptr, nullptr, nullptr,
                gb + D, nullptr, nullptr, nullptr, h0, l0, 1, 1, M_PLAIN, D, 0 };
    GJob G2 = { h1, l1, nullptr, nullptr, nullptr, nullptr,
                gb + 2 * D, nullptr, nullptr, nullptr, h0, l0, 2, 1, M_PLAIN, D, 0 };
    // S jobs (SAGE, pool fused as chunk 1)
    GJob S0 = { xh, xl, nullptr, nullptr, nullptr, nullptr,
                pb, nullptr, nullptr, nullptr, h2, l2, 3, 1, M_RELU, D, 0 };
    GJob S1 = { xh, xl, h2, l2, nullptr, nullptr,
                mb, nullptr, nullptr, nullptr, h3, l3, 4, 2, M_RELU, D, 0 };
    GJob S2 = { h3, l3, h3, l3, h3, l3,
                mb + D, slg, slb, nullptr, h2, l2, 6, 2, M_LN, D, 0 };
    GJob S3 = { h2, l2, h2, l2, h2, l2,
                mb + 2 * D, slg + D, slb + D, out, nullptr, nullptr,
                8, 2, M_LN, 2 * D, D };
    // P jobs
    PJob P0 = { h0, l0, h0, l0, glg,         glb,         nullptr, h1, l1, D, 0 };
    PJob P1 = { h0, l0, h1, l1, glg + D,     glb + D,     nullptr, h1, l1, D, 0 };
    PJob P2 = { h0, l0, h1, l1, glg + 2 * D, glb + 2 * D, out, nullptr, nullptr,
                2 * D, 0 };

    prep_all_kernel<<<106, 256>>>(nei, nbc, gW, pW, mW, x);

    k_g2<<<2 * GB, THREADS, SMEM_TOTAL>>>(G0, S0);       // step1: G0 | S0
    k_gp<<<GB + PB, THREADS, SMEM_TOTAL>>>(S1, P0);      // step2: S1 | P0
    k_g2<<<2 * GB, THREADS, SMEM_TOTAL>>>(G1, S2);       // step3: G1 | S2
    k_gp<<<GB + PB, THREADS, SMEM_TOTAL>>>(S3, P1);      // step4: S3 | P1
    k_g1<<<GB, THREADS, SMEM_TOTAL>>>(G2);               // step5: G2
    k_p<<<PB, THREADS>>>(P2);                            // step6: P2
}